// round 11
// baseline (speedup 1.0000x reference)
#include <cuda_runtime.h>
#include <cstdint>

#define DIMC 384
#define G     96        // channels per CTA (cluster of 4 covers 384)
#define NP    49
#define PITCH 196       // floats per channel: 4 pixels x 49
#define NT    672       // 21 warps; 4704 f4 per buffer = exactly 7/thread
#define BUF_F 18816     // floats per buffer (96*196)
#define NCL   33        // clusters resident (cluster-4 cap = 132 CTAs)
#define NITEMS 512      // 8 b * 16 h * 4 pixel-quads

#define CP_ASYNC_CG(dst, src) \
    asm volatile("cp.async.cg.shared.global [%0], [%1], 16;" \
                 :: "r"(dst), "l"(src) : "memory")
#define CP_COMMIT() asm volatile("cp.async.commit_group;" ::: "memory")
#define CP_WAIT(N)  asm volatile("cp.async.wait_group %0;" :: "n"(N) : "memory")

__global__ void __launch_bounds__(NT, 1) __cluster_dims__(4, 1, 1)
attn_ds_kernel(
    const float* __restrict__ hr,   // (8, 384, 112, 112)
    const float* __restrict__ du,   // (8, 16, 16, 1)
    const float* __restrict__ aw,   // (384,)
    const float* __restrict__ ab,   // (1,)
    const float* __restrict__ wt,   // (7,7) -> 49
    const float* __restrict__ bt,   // (7,7) -> 49
    float* __restrict__ out)        // (8, 384, 16, 16)
{
    extern __shared__ float s_raw[];          // 2 x [96][196] = 150528 B
    __shared__ float s_pl[3][196];            // phase-2 sub-partials
    __shared__ float s_red[2][4][196];        // partials x parity (DSMEM targets)
    __shared__ float s_attn[196];
    __shared__ float s_aw[G];

    const int tid  = threadIdx.x;
    const int lane = tid & 31;
    const int wid  = tid >> 5;
    const int rank = blockIdx.x & 3;          // channel quarter
    const int cid  = blockIdx.x >> 2;         // cluster id 0..32
    const int c0   = rank * G;

    if (tid < G) s_aw[tid] = aw[c0 + tid];

    const uint32_t sm_u32 = (uint32_t)__cvta_generic_to_shared(s_raw);
    const float4* hr4 = (const float4*)hr;

    // Hoisted per-thread load decomposition (item-independent):
    //   c = idx/49 via (idx*42800)>>21; rw = rm/7 via (rm*9363)>>16.
    unsigned goff[7];
    #pragma unroll
    for (int i = 0; i < 7; ++i) {
        unsigned idx = (unsigned)tid + i * NT;
        unsigned c  = (idx * 42800u) >> 21;
        unsigned rm = idx - c * 49u;
        unsigned rw = (rm * 9363u) >> 16;
        unsigned fc = rm - rw * 7u;
        goff[i] = c * 3136u + rw * 28u + fc;  // float4 offset within quad block
    }

    // Issue one item's 75KB as cp.async.cg (L1-bypass, register-free).
    auto issue = [&](int item, int buf) {
        const int strip = item >> 2, q = item & 3;
        const int b = strip >> 4, h = strip & 15;
        const float4* gs = hr4 + ((size_t)(b * DIMC + c0)) * 3136
                               + (size_t)h * 196 + q * 7;
        const uint32_t dbase = sm_u32 + (unsigned)buf * (BUF_F * 4);
        #pragma unroll
        for (int i = 0; i < 7; ++i)
            CP_ASYNC_CG(dbase + ((unsigned)tid + i * NT) * 16u, gs + goff[i]);
        CP_COMMIT();
    };

    int buf = 0, par = 0;
    issue(cid, 0);                            // prologue prefetch

    for (int item = cid; item < NITEMS; item += NCL) {
        const int nxt = item + NCL;
        if (nxt < NITEMS) { issue(nxt, buf ^ 1); CP_WAIT(1); }
        else              { CP_WAIT(0); }
        __syncthreads();                      // buffer `buf` ready for all

        const float* sb = s_raw + buf * BUF_F;
        const int strip = item >> 2, q = item & 3;
        const int b = strip >> 4, h = strip & 15;

        // ---- Phase 2: partial logits over this CTA's 96 channels ----
        // 21 warps: g = wid%7 (p-row), cc = wid/7; lane<28 -> (pp, w).
        // Banks pp + 7w distinct over 28 lanes -> conflict-free.
        if (lane < 28) {
            const int g   = wid % 7;
            const int cc  = wid / 7;
            const int off = 28 * g + (lane >> 2) + 7 * (lane & 3);
            const int cb  = cc * 32;
            float a0 = 0.0f, a1 = 0.0f;
            #pragma unroll
            for (int i = 0; i < 32; i += 2) {
                a0 = fmaf(sb[(cb + i)     * PITCH + off], s_aw[cb + i],     a0);
                a1 = fmaf(sb[(cb + i + 1) * PITCH + off], s_aw[cb + i + 1], a1);
            }
            s_pl[cc][g * 28 + lane] = a0 + a1;        // index == 4p + w
        }
        __syncthreads();

        // ---- Combine sub-partials; push to 3 peer CTAs (parity buffer) ----
        if (tid < 196) {
            float t = s_pl[0][tid] + s_pl[1][tid] + s_pl[2][tid];
            s_red[par][rank][tid] = t;
            uint32_t loc = (uint32_t)__cvta_generic_to_shared(&s_red[par][rank][tid]);
            #pragma unroll
            for (int pr = 0; pr < 4; ++pr) {
                if (pr == rank) continue;
                uint32_t rem;
                asm ("mapa.shared::cluster.u32 %0, %1, %2;"
                     : "=r"(rem) : "r"(loc), "r"(pr));
                asm volatile("st.shared::cluster.f32 [%0], %1;"
                             :: "r"(rem), "f"(t) : "memory");
            }
        }
        asm volatile("barrier.cluster.arrive.aligned;" ::: "memory");
        asm volatile("barrier.cluster.wait.aligned;"   ::: "memory");

        // ---- Softmax: warp wid handles pixel w = wid ----
        if (wid < 4) {
            const int w = wid;
            const float m   = (du[(strip << 4) + (q << 2) + w] > 0.2f) ? 1.0f : 0.0f;
            const float a0c = ab[0];
            const int p1 = lane + 32;
            float l0 = (s_red[par][0][4 * lane + w] + s_red[par][1][4 * lane + w]
                      + s_red[par][2][4 * lane + w] + s_red[par][3][4 * lane + w]
                      + a0c) * m * wt[lane] + bt[lane];
            float l1 = (p1 < NP)
                     ? (s_red[par][0][4 * p1 + w] + s_red[par][1][4 * p1 + w]
                      + s_red[par][2][4 * p1 + w] + s_red[par][3][4 * p1 + w]
                      + a0c) * m * wt[p1] + bt[p1]
                     : -1e30f;
            float mx = fmaxf(l0, l1);
            #pragma unroll
            for (int o = 16; o > 0; o >>= 1)
                mx = fmaxf(mx, __shfl_xor_sync(0xffffffffu, mx, o));
            float e0 = __expf(l0 - mx);
            float e1 = (p1 < NP) ? __expf(l1 - mx) : 0.0f;
            float s = e0 + e1;
            #pragma unroll
            for (int o = 16; o > 0; o >>= 1)
                s += __shfl_xor_sync(0xffffffffu, s, o);
            const float inv = 1.0f / s;
            s_attn[4 * lane + w] = e0 * inv;
            if (p1 < NP) s_attn[4 * p1 + w] = e1 * inv;
        }
        __syncthreads();

        // ---- Phase 4: out[c][w] = sum_p patch * attn; thread = (c, w) ----
        // Banks 4*(lane>>2) + 7*(lane&3) bijective over 32 -> conflict-free.
        if (tid < 384) {
            const int c = tid >> 2;
            const int w = tid & 3;
            const float* sp = sb + c * PITCH + 7 * w;
            float a0 = 0.0f, a1 = 0.0f;
            #pragma unroll
            for (int p = 0; p < NP; ++p) {
                const int off = (p / 7) * 28 + (p % 7);   // compile-time
                if (p & 1) a1 = fmaf(sp[off], s_attn[4 * p + w], a1);
                else       a0 = fmaf(sp[off], s_attn[4 * p + w], a0);
            }
            __stcg(&out[(((size_t)(b * DIMC + c0 + c)) << 8)
                        + (h << 4) + (q << 2) + w], a0 + a1);
        }
        __syncthreads();                      // phase-4 done before buf reuse

        buf ^= 1; par ^= 1;
    }
}

extern "C" void kernel_launch(void* const* d_in, const int* in_sizes, int n_in,
                              void* d_out, int out_size)
{
    const float* hr = (const float*)d_in[0];  // hr_feats
    // d_in[1] = guidance (unused, zeros)
    const float* du = (const float*)d_in[2];  // dropout_u
    const float* aw = (const float*)d_in[3];
    const float* ab = (const float*)d_in[4];
    const float* wt = (const float*)d_in[5];
    const float* bt = (const float*)d_in[6];
    float* out = (float*)d_out;

    const size_t smem = 2ull * BUF_F * sizeof(float);   // 150528 B (double buf)
    cudaFuncSetAttribute(attn_ds_kernel,
                         cudaFuncAttributeMaxDynamicSharedMemorySize, (int)smem);
    // 33 persistent clusters x 4 CTAs = 132 CTAs (cluster-4 residency cap):
    // one wave, each cluster loops ~16 items with cp.async double buffering.
    attn_ds_kernel<<<4 * NCL, NT, smem>>>(hr, du, aw, ab, wt, bt, out);
}

// round 12
// speedup vs baseline: 1.1782x; 1.1782x over previous
#include <cuda_runtime.h>
#include <cstdint>

#define DIMC 384
#define G     96         // channels per CTA (cluster of 4 covers 384)
#define NP    49
#define PITCH 196        // floats per channel: 4 pixels x 49
#define NT    672        // 21 warps; 96*49 = 4704 f4 = exactly 7 per thread

#define CP_ASYNC_CG(dst, src) \
    asm volatile("cp.async.cg.shared.global [%0], [%1], 16;" \
                 :: "r"(dst), "l"(src) : "memory")
#define CP_COMMIT() asm volatile("cp.async.commit_group;" ::: "memory")
#define CP_WAIT0()  asm volatile("cp.async.wait_group 0;" ::: "memory")

__global__ void __launch_bounds__(NT, 2) __cluster_dims__(4, 1, 1)
attn_ds_kernel(
    const float* __restrict__ hr,   // (8, 384, 112, 112)
    const float* __restrict__ du,   // (8, 16, 16, 1)
    const float* __restrict__ aw,   // (384,)
    const float* __restrict__ ab,   // (1,)
    const float* __restrict__ wt,   // (7,7) -> 49
    const float* __restrict__ bt,   // (7,7) -> 49
    float* __restrict__ out)        // (8, 384, 16, 16)
{
    extern __shared__ float s_raw[];          // [96][196] = 75264 B
    __shared__ float s_pl[3][196];            // phase-2 sub-partials
    __shared__ float s_red[4][196];           // partials from all 4 ranks
    __shared__ float s_attn[196];             // attn weights [p*4+w]
    __shared__ float s_aw[G];

    const int tid  = threadIdx.x;
    const int lane = tid & 31;
    const int wid  = tid >> 5;
    const int rank = blockIdx.x & 3;          // channel quarter
    const int grp  = blockIdx.x >> 2;         // (b*16+h)*4 + q
    const int q    = grp & 3;                 // pixel-quad: pixels 4q..4q+3
    const int strip= grp >> 2;                // b*16 + h
    const int b = strip >> 4, h = strip & 15;
    const int c0 = rank * G;

    if (tid < G) s_aw[tid] = aw[c0 + tid];

    // Channel c's 4-pixel patch row = 28 contiguous floats = 7 aligned float4.
    const float4* gsrc = (const float4*)hr
        + ((size_t)(b * DIMC + c0)) * 3136 + (size_t)h * 196 + q * 7;
    const uint32_t sbase = (uint32_t)__cvta_generic_to_shared(s_raw);

    // ---- Load: 4704 f4 via cp.async.cg (L1-bypass, no reg round-trip) ----
    //   c = idx/49 via (idx*42800)>>21 (exact idx<43690); rw = rm/7 via
    //   (rm*9363)>>16. SMEM float layout per channel: rw*28 + col (natural).
    #pragma unroll
    for (int i = 0; i < 7; ++i) {
        unsigned idx = (unsigned)tid + i * NT;
        unsigned c  = (idx * 42800u) >> 21;
        unsigned rm = idx - c * 49u;
        unsigned rw = (rm * 9363u) >> 16;
        unsigned fc = rm - rw * 7u;
        CP_ASYNC_CG(sbase + idx * 16u, gsrc + ((size_t)c * 3136 + rw * 28 + fc));
    }
    CP_COMMIT();
    CP_WAIT0();
    __syncthreads();

    // ---- Phase 2: partial logits over this CTA's 96 channels ----
    // 21 warps: g = wid%7 (p-row), cc = wid/7 (32-channel group); lane<28 ->
    // (pp = lane>>2, w = lane&3), off = 28g + pp + 7w.
    // Banks pp + 7w distinct over 28 lanes -> conflict-free.
    if (lane < 28) {
        const int g   = wid % 7;
        const int cc  = wid / 7;              // 0..2
        const int off = 28 * g + (lane >> 2) + 7 * (lane & 3);
        const int cb  = cc * 32;
        float a0 = 0.0f, a1 = 0.0f;
        #pragma unroll
        for (int i = 0; i < 32; i += 2) {
            a0 = fmaf(s_raw[(cb + i)     * PITCH + off], s_aw[cb + i],     a0);
            a1 = fmaf(s_raw[(cb + i + 1) * PITCH + off], s_aw[cb + i + 1], a1);
        }
        s_pl[cc][g * 28 + lane] = a0 + a1;    // index == 4p + w
    }
    __syncthreads();

    // ---- Combine 3 sub-partials; push to 3 peer CTAs ----
    if (tid < 196) {
        float t = s_pl[0][tid] + s_pl[1][tid] + s_pl[2][tid];
        s_red[rank][tid] = t;                 // own slot locally
        uint32_t loc = (uint32_t)__cvta_generic_to_shared(&s_red[rank][tid]);
        #pragma unroll
        for (int pr = 0; pr < 4; ++pr) {
            if (pr == rank) continue;
            uint32_t rem;
            asm ("mapa.shared::cluster.u32 %0, %1, %2;" : "=r"(rem) : "r"(loc), "r"(pr));
            asm volatile("st.shared::cluster.f32 [%0], %1;" :: "r"(rem), "f"(t) : "memory");
        }
    }
    // Cluster barrier: releases our remote stores, acquires peers' stores.
    asm volatile("barrier.cluster.arrive.aligned;" ::: "memory");
    asm volatile("barrier.cluster.wait.aligned;"   ::: "memory");

    // ---- Softmax: warp wid handles pixel w = wid (4 pixels) ----
    if (wid < 4) {
        const int w = wid;
        const float m   = (du[(strip << 4) + (q << 2) + w] > 0.2f) ? 1.0f : 0.0f;
        const float a0c = ab[0];
        const int p1 = lane + 32;
        float l0 = (s_red[0][4 * lane + w] + s_red[1][4 * lane + w]
                  + s_red[2][4 * lane + w] + s_red[3][4 * lane + w] + a0c)
                   * m * wt[lane] + bt[lane];
        float l1 = (p1 < NP)
                 ? (s_red[0][4 * p1 + w] + s_red[1][4 * p1 + w]
                  + s_red[2][4 * p1 + w] + s_red[3][4 * p1 + w] + a0c)
                   * m * wt[p1] + bt[p1]
                 : -1e30f;
        float mx = fmaxf(l0, l1);
        #pragma unroll
        for (int o = 16; o > 0; o >>= 1)
            mx = fmaxf(mx, __shfl_xor_sync(0xffffffffu, mx, o));
        float e0 = __expf(l0 - mx);
        float e1 = (p1 < NP) ? __expf(l1 - mx) : 0.0f;
        float s = e0 + e1;
        #pragma unroll
        for (int o = 16; o > 0; o >>= 1)
            s += __shfl_xor_sync(0xffffffffu, s, o);
        const float inv = 1.0f / s;
        s_attn[4 * lane + w] = e0 * inv;
        if (p1 < NP) s_attn[4 * p1 + w] = e1 * inv;
    }
    __syncthreads();

    // ---- Phase 4: out[c][w] = sum_p patch * attn; thread = (c, w) ----
    // Banks 4*(lane>>2) + 7*(lane&3) distinct over 32 lanes -> conflict-free.
    if (tid < 384) {
        const int c = tid >> 2;               // 0..95
        const int w = tid & 3;
        const float* sp = s_raw + c * PITCH + 7 * w;
        float a0 = 0.0f, a1 = 0.0f;
        #pragma unroll
        for (int p = 0; p < NP; ++p) {
            const int off = (p / 7) * 28 + (p % 7);   // compile-time
            if (p & 1) a1 = fmaf(sp[off], s_attn[4 * p + w], a1);
            else       a0 = fmaf(sp[off], s_attn[4 * p + w], a0);
        }
        __stcg(&out[(((size_t)(b * DIMC + c0 + c)) << 8) + (h << 4) + (q << 2) + w],
               a0 + a1);
    }
}

extern "C" void kernel_launch(void* const* d_in, const int* in_sizes, int n_in,
                              void* d_out, int out_size)
{
    const float* hr = (const float*)d_in[0];  // hr_feats
    // d_in[1] = guidance (unused, zeros)
    const float* du = (const float*)d_in[2];  // dropout_u
    const float* aw = (const float*)d_in[3];
    const float* ab = (const float*)d_in[4];
    const float* wt = (const float*)d_in[5];
    const float* bt = (const float*)d_in[6];
    float* out = (float*)d_out;

    const size_t smem = (size_t)G * PITCH * sizeof(float);  // 75264 B
    cudaFuncSetAttribute(attn_ds_kernel,
                         cudaFuncAttributeMaxDynamicSharedMemorySize, (int)smem);
    // 128 strips x 4 quads x 4-CTA clusters = 2048 CTAs; 2 CTAs/SM for
    // cross-CTA load/compute overlap (R10 structure + cp.async loads).
    attn_ds_kernel<<<2048, NT, smem>>>(hr, du, aw, ab, wt, bt, out);
}

// round 13
// speedup vs baseline: 1.2782x; 1.0849x over previous
#include <cuda_runtime.h>
#include <cstdint>

#define DIMC 384
#define G     96         // channels per CTA (cluster of 4 covers 384)
#define NP    49
#define PITCH 196        // floats per channel: 4 pixels x 49
#define NT    672        // 21 warps
#define CHUNK_F4 1568    // 32 channels x 49 float4 per chunk

#define CP_ASYNC_CG(dst, src) \
    asm volatile("cp.async.cg.shared.global [%0], [%1], 16;" \
                 :: "r"(dst), "l"(src) : "memory")
#define CP_COMMIT() asm volatile("cp.async.commit_group;" ::: "memory")
#define CP_WAIT(N)  asm volatile("cp.async.wait_group %0;" :: "n"(N) : "memory")

__global__ void __launch_bounds__(NT, 2) __cluster_dims__(4, 1, 1)
attn_ds_kernel(
    const float* __restrict__ hr,   // (8, 384, 112, 112)
    const float* __restrict__ du,   // (8, 16, 16, 1)
    const float* __restrict__ aw,   // (384,)
    const float* __restrict__ ab,   // (1,)
    const float* __restrict__ wt,   // (7,7) -> 49
    const float* __restrict__ bt,   // (7,7) -> 49
    float* __restrict__ out)        // (8, 384, 16, 16)
{
    extern __shared__ float s_raw[];          // [96][196] = 75264 B
    __shared__ float s_pl[3][196];            // phase-2 sub-partials
    __shared__ float s_red[4][196];           // partials from all 4 ranks
    __shared__ float s_attn[196];             // attn weights [p*4+w]
    __shared__ float s_aw[G];

    const int tid  = threadIdx.x;
    const int lane = tid & 31;
    const int wid  = tid >> 5;
    const int rank = blockIdx.x & 3;          // channel quarter
    const int grp  = blockIdx.x >> 2;         // (b*16+h)*4 + q
    const int q    = grp & 3;                 // pixel-quad: pixels 4q..4q+3
    const int strip= grp >> 2;                // b*16 + h
    const int b = strip >> 4, h = strip & 15;
    const int c0 = rank * G;

    if (tid < G) s_aw[tid] = aw[c0 + tid];

    // Channel c's 4-pixel patch row = 28 contiguous floats = 7 aligned float4.
    const float4* gsrc = (const float4*)hr
        + ((size_t)(b * DIMC + c0)) * 3136 + (size_t)h * 196 + q * 7;
    const uint32_t sbase = (uint32_t)__cvta_generic_to_shared(s_raw);

    // ---- Load: 3 chunks of 32 channels, one cp.async commit-group each ----
    //   c = idx/49 via (idx*42800)>>21 (exact idx<43690); rw = rm/7 via
    //   (rm*9363)>>16. Chunk cc covers channels [32cc, 32cc+32) so warp-group
    //   cc's phase-2 input arrives in commit-group cc.
    #pragma unroll
    for (int cc = 0; cc < 3; ++cc) {
        #pragma unroll
        for (int i = 0; i < 3; ++i) {
            unsigned loc = (unsigned)tid + i * NT;
            if (i < 2 || tid < CHUNK_F4 - 2 * NT) {       // 1568 = 2*672 + 224
                unsigned c  = (loc * 42800u) >> 21;
                unsigned rm = loc - c * 49u;
                unsigned rw = (rm * 9363u) >> 16;
                unsigned fc = rm - rw * 7u;
                CP_ASYNC_CG(sbase + (cc * CHUNK_F4 + loc) * 16u,
                            gsrc + ((size_t)(cc * 32 + c) * 3136 + rw * 28 + fc));
            }
        }
        CP_COMMIT();
    }

    // ---- Phase 2, progressively gated: group cc computes once chunk cc lands.
    // 21 warps: g = wid%7 (p-row), cc = wid/7; lane<28 -> (pp, w),
    // off = 28g + pp + 7w. Banks pp + 7w distinct over 28 lanes: conflict-free.
    const int g   = wid % 7;
    const int cc  = wid / 7;
    const int off = 28 * g + (lane >> 2) + 7 * (lane & 3);

    CP_WAIT(2);  __syncthreads();             // chunk 0 visible
    if (cc == 0 && lane < 28) {
        float a0 = 0.0f, a1 = 0.0f;
        #pragma unroll
        for (int i = 0; i < 32; i += 2) {
            a0 = fmaf(s_raw[i       * PITCH + off], s_aw[i],     a0);
            a1 = fmaf(s_raw[(i + 1) * PITCH + off], s_aw[i + 1], a1);
        }
        s_pl[0][g * 28 + lane] = a0 + a1;     // index == 4p + w
    }
    CP_WAIT(1);  __syncthreads();             // chunk 1 visible
    if (cc == 1 && lane < 28) {
        float a0 = 0.0f, a1 = 0.0f;
        #pragma unroll
        for (int i = 32; i < 64; i += 2) {
            a0 = fmaf(s_raw[i       * PITCH + off], s_aw[i],     a0);
            a1 = fmaf(s_raw[(i + 1) * PITCH + off], s_aw[i + 1], a1);
        }
        s_pl[1][g * 28 + lane] = a0 + a1;
    }
    CP_WAIT(0);  __syncthreads();             // chunk 2 visible
    if (cc == 2 && lane < 28) {
        float a0 = 0.0f, a1 = 0.0f;
        #pragma unroll
        for (int i = 64; i < 96; i += 2) {
            a0 = fmaf(s_raw[i       * PITCH + off], s_aw[i],     a0);
            a1 = fmaf(s_raw[(i + 1) * PITCH + off], s_aw[i + 1], a1);
        }
        s_pl[2][g * 28 + lane] = a0 + a1;
    }
    __syncthreads();                          // all s_pl written

    // ---- Combine 3 sub-partials; push to 3 peer CTAs ----
    if (tid < 196) {
        float t = s_pl[0][tid] + s_pl[1][tid] + s_pl[2][tid];
        s_red[rank][tid] = t;                 // own slot locally
        uint32_t loc = (uint32_t)__cvta_generic_to_shared(&s_red[rank][tid]);
        #pragma unroll
        for (int pr = 0; pr < 4; ++pr) {
            if (pr == rank) continue;
            uint32_t rem;
            asm ("mapa.shared::cluster.u32 %0, %1, %2;" : "=r"(rem) : "r"(loc), "r"(pr));
            asm volatile("st.shared::cluster.f32 [%0], %1;" :: "r"(rem), "f"(t) : "memory");
        }
    }
    // Cluster barrier: releases our remote stores, acquires peers' stores.
    asm volatile("barrier.cluster.arrive.aligned;" ::: "memory");
    asm volatile("barrier.cluster.wait.aligned;"   ::: "memory");

    // ---- Softmax: warp wid handles pixel w = wid (4 pixels) ----
    if (wid < 4) {
        const int w = wid;
        const float m   = (du[(strip << 4) + (q << 2) + w] > 0.2f) ? 1.0f : 0.0f;
        const float a0c = ab[0];
        const int p1 = lane + 32;
        float l0 = (s_red[0][4 * lane + w] + s_red[1][4 * lane + w]
                  + s_red[2][4 * lane + w] + s_red[3][4 * lane + w] + a0c)
                   * m * wt[lane] + bt[lane];
        float l1 = (p1 < NP)
                 ? (s_red[0][4 * p1 + w] + s_red[1][4 * p1 + w]
                  + s_red[2][4 * p1 + w] + s_red[3][4 * p1 + w] + a0c)
                   * m * wt[p1] + bt[p1]
                 : -1e30f;
        float mx = fmaxf(l0, l1);
        #pragma unroll
        for (int o = 16; o > 0; o >>= 1)
            mx = fmaxf(mx, __shfl_xor_sync(0xffffffffu, mx, o));
        float e0 = __expf(l0 - mx);
        float e1 = (p1 < NP) ? __expf(l1 - mx) : 0.0f;
        float s = e0 + e1;
        #pragma unroll
        for (int o = 16; o > 0; o >>= 1)
            s += __shfl_xor_sync(0xffffffffu, s, o);
        const float inv = 1.0f / s;
        s_attn[4 * lane + w] = e0 * inv;
        if (p1 < NP) s_attn[4 * p1 + w] = e1 * inv;
    }
    __syncthreads();

    // ---- Phase 4: out[c][w] = sum_p patch * attn; thread = (c, w) ----
    // Banks 4*(lane>>2) + 7*(lane&3) distinct over 32 lanes -> conflict-free.
    if (tid < 384) {
        const int c = tid >> 2;               // 0..95
        const int w = tid & 3;
        const float* sp = s_raw + c * PITCH + 7 * w;
        float a0 = 0.0f, a1 = 0.0f;
        #pragma unroll
        for (int p = 0; p < NP; ++p) {
            const int poff = (p / 7) * 28 + (p % 7);   // compile-time
            if (p & 1) a1 = fmaf(sp[poff], s_attn[4 * p + w], a1);
            else       a0 = fmaf(sp[poff], s_attn[4 * p + w], a0);
        }
        __stcg(&out[(((size_t)(b * DIMC + c0 + c)) << 8) + (h << 4) + (q << 2) + w],
               a0 + a1);
    }
}

extern "C" void kernel_launch(void* const* d_in, const int* in_sizes, int n_in,
                              void* d_out, int out_size)
{
    const float* hr = (const float*)d_in[0];  // hr_feats
    // d_in[1] = guidance (unused, zeros)
    const float* du = (const float*)d_in[2];  // dropout_u
    const float* aw = (const float*)d_in[3];
    const float* ab = (const float*)d_in[4];
    const float* wt = (const float*)d_in[5];
    const float* bt = (const float*)d_in[6];
    float* out = (float*)d_out;

    const size_t smem = (size_t)G * PITCH * sizeof(float);  // 75264 B
    cudaFuncSetAttribute(attn_ds_kernel,
                         cudaFuncAttributeMaxDynamicSharedMemorySize, (int)smem);
    // 128 strips x 4 quads x 4-CTA clusters = 2048 CTAs; 2 CTAs/SM, with
    // chunked cp.async so phase-2 starts after 1/3 of the load.
    attn_ds_kernel<<<2048, NT, smem>>>(hr, du, aw, ab, wt, bt, out);
}